// round 5
// baseline (speedup 1.0000x reference)
#include <cuda_runtime.h>
#include <cstdint>

// Problem constants: features (B, D, L) f32, tois (B, N, 2) i32, MAX_SPAN=64
#define BB 16
#define DD 256
#define LL 4096
#define NQ 4096
#define CHUNKS 63            // c0 = start>>6 in [0,62] since start <= L-MAX_SPAN-1
#define CAP 192              // bin capacity; mean occupancy ~65, >10 sigma margin

// Binning scratch (no big scratch anymore — scan lives in smem)
__device__ int g_cnt[BB * CHUNKS];
__device__ int g_bins[BB * CHUNKS * CAP];

// ---------------------------------------------------------------------------
// Prepass 1: zero bin counters
// ---------------------------------------------------------------------------
__global__ void k_zero() {
    const int i = threadIdx.x + blockIdx.x * blockDim.x;
    if (i < BB * CHUNKS) g_cnt[i] = 0;
}

// ---------------------------------------------------------------------------
// Prepass 2: scatter query ids into (b, start-chunk) bins
// ---------------------------------------------------------------------------
__global__ void k_binfill(const int* __restrict__ tois) {
    const int q = threadIdx.x + blockIdx.x * blockDim.x;   // 0..B*N-1
    const int start = tois[2 * q];
    const int bin = (q >> 12) * CHUNKS + (start >> 6);
    const int pos = atomicAdd(&g_cnt[bin], 1);
    if (pos < CAP) g_bins[bin * CAP + pos] = q;
}

// ---------------------------------------------------------------------------
// Main fused kernel. Block = (c0, d-slice h, b).
// Phase A: load feat[l0..l0+128) x 64 d-rows, chunk-local (64) inclusive scan
//          along l, store transposed into smem ic[d][l] (129-float rows:
//          conflict-free column reads in phase B).
// Phase B: serve every query in bin (b, c0) from smem: head/avg/tail for this
//          block's 64-d slice. 4 queries in flight (64 threads each).
// ---------------------------------------------------------------------------
__global__ void __launch_bounds__(256) k_main(const float* __restrict__ feat,
                                              const int* __restrict__ tois,
                                              float* __restrict__ out,
                                              int write_counts) {
    __shared__ float ic[64][129];     // [d][l], pad 1 -> bank (d+l)%32

    const int c0 = blockIdx.x;        // 0..62
    const int h  = blockIdx.y;        // d slice 0..3 (64 d each)
    const int b  = blockIdx.z;
    const int tid  = threadIdx.x;
    const int w    = tid >> 5;
    const int lane = tid & 31;
    const int l0   = c0 << 6;

    // ---- Phase A: 8 warps x 8 d-rows; lane owns float4 of l (128 l total).
    // width-16 shuffle scan restarts exactly at the 64-l chunk boundary.
    #pragma unroll
    for (int r = 0; r < 8; r++) {
        const int dd = (w << 3) + r;                   // local d row 0..63
        const int dg = (h << 6) + dd;                  // global d
        const float4 v = *reinterpret_cast<const float4*>(
            feat + ((size_t)b * DD + dg) * LL + l0 + 4 * lane);
        const float i0 = v.x;
        const float i1 = i0 + v.y;
        const float i2 = i1 + v.z;
        const float i3 = i2 + v.w;
        float s = i3;
        #pragma unroll
        for (int o = 1; o < 16; o <<= 1) {
            const float t = __shfl_up_sync(0xffffffffu, s, o, 16);
            if ((lane & 15) >= o) s += t;
        }
        const float pre = s - i3;                      // exclusive prefix in chunk
        ic[dd][4 * lane    ] = pre + i0;
        ic[dd][4 * lane + 1] = pre + i1;
        ic[dd][4 * lane + 2] = pre + i2;
        ic[dd][4 * lane + 3] = pre + i3;
    }
    __syncthreads();

    // ---- Phase B: queries of bin (b, c0); groups of 64 threads per query.
    const int bin = b * CHUNKS + c0;
    const int cnt = min(g_cnt[bin], CAP);
    const int ofs = bin * CAP;
    const int grp = tid >> 6;          // 0..3
    const int t64 = tid & 63;          // local d = t64

    for (int i = grp; i < cnt; i += 4) {
        const int q = g_bins[ofs + i];
        const int2 t = __ldg(reinterpret_cast<const int2*>(tois) + q);
        const int sL = t.x - l0;           // [0,64)
        const int eL = t.y - 1 - l0;       // [0,127]

        const float A  = ic[t64][sL];
        const float Bv = sL        ? ic[t64][sL - 1] : 0.0f;
        const float C  = ic[t64][eL];
        const float Dv = (eL & 63) ? ic[t64][eL - 1] : 0.0f;
        const float E  = (eL >= 64) ? ic[t64][63]    : 0.0f;

        const float head = A - Bv;
        const float tail = C - Dv;
        const float avg  = (C + E - Bv) / (float)(t.y - t.x);

        float* o = out + (size_t)q * (3 * DD) + (h << 6) + t64;
        o[0]        = head;
        o[DD]       = avg;
        o[2 * DD]   = tail;
    }

    // counts output: cumsum of per-batch query counts = [N, 2N, ..., B*N]
    if (write_counts && c0 == 0 && h == 0 && b == 0 && tid < BB) {
        out[(size_t)BB * NQ * 3 * DD + tid] = (float)((tid + 1) * NQ);
    }
}

extern "C" void kernel_launch(void* const* d_in, const int* in_sizes, int n_in,
                              void* d_out, int out_size) {
    const float* feat = (const float*)d_in[0];
    const int*   tois = (const int*)d_in[1];
    float*       out  = (float*)d_out;

    const long long total = (long long)BB * NQ * 3 * DD;  // 50,331,648
    const int write_counts = ((long long)out_size >= total + BB) ? 1 : 0;

    k_zero<<<(BB * CHUNKS + 255) / 256, 256>>>();
    k_binfill<<<(BB * NQ) / 256, 256>>>(tois);

    dim3 g(CHUNKS, 4, BB);            // 63 x 4 x 16 = 4032 blocks
    k_main<<<g, 256>>>(feat, tois, out, write_counts);
}

// round 6
// speedup vs baseline: 1.1215x; 1.1215x over previous
#include <cuda_runtime.h>
#include <cstdint>

// Problem constants: features (B, D, L) f32, tois (B, N, 2) i32, MAX_SPAN=64
#define BB 16
#define DD 256
#define LL 4096
#define NQ 4096
#define CHUNKS 63            // c0 = start>>6 in [0,62] since start <= L-MAX_SPAN-1
#define CAP 192              // bin capacity; mean occupancy ~65, >10 sigma margin

__device__ int g_cnt[BB * CHUNKS];
__device__ int g_bins[BB * CHUNKS * CAP];

// ---------------------------------------------------------------------------
// Prepass: per-batch binning entirely in one kernel (smem histogram+scatter).
// One block per b; 1024 threads x 4 queries each.
// ---------------------------------------------------------------------------
__global__ void __launch_bounds__(1024) k_prep(const int* __restrict__ tois) {
    __shared__ int hist[CHUNKS];
    __shared__ int cur[CHUNKS];

    const int b   = blockIdx.x;
    const int tid = threadIdx.x;

    if (tid < CHUNKS) { hist[tid] = 0; cur[tid] = 0; }
    __syncthreads();

    int c[4];
    #pragma unroll
    for (int k = 0; k < 4; k++) {
        const int n = tid + (k << 10);
        const int s = tois[((size_t)b * NQ + n) * 2];
        c[k] = s >> 6;
        atomicAdd(&hist[c[k]], 1);
    }
    __syncthreads();

    if (tid < CHUNKS) g_cnt[b * CHUNKS + tid] = hist[tid];

    #pragma unroll
    for (int k = 0; k < 4; k++) {
        const int n = tid + (k << 10);
        const int p = atomicAdd(&cur[c[k]], 1);
        if (p < CAP) g_bins[(b * CHUNKS + c[k]) * CAP + p] = b * NQ + n;
    }
}

// ---------------------------------------------------------------------------
// Main fused kernel. Block = (c0, d-slice h, b).
// Stage bin metadata into smem (overlaps scan), chunk-local scan of
// feat[l0..l0+128) x 64 d into smem, then serve queries from smem only.
// ---------------------------------------------------------------------------
__global__ void __launch_bounds__(256) k_main(const float* __restrict__ feat,
                                              const int* __restrict__ tois,
                                              float* __restrict__ out,
                                              int write_counts) {
    __shared__ float ic[64][129];     // [d][l]; column reads conflict-free
    __shared__ int   s_qid[CAP];
    __shared__ int2  s_toi[CAP];

    const int c0 = blockIdx.x;        // 0..62
    const int h  = blockIdx.y;        // d slice 0..3
    const int b  = blockIdx.z;
    const int tid  = threadIdx.x;
    const int w    = tid >> 5;
    const int lane = tid & 31;
    const int l0   = c0 << 6;

    // ---- Stage bin metadata (all threads read same g_cnt addr: broadcast).
    const int bin = b * CHUNKS + c0;
    const int cnt = min(g_cnt[bin], CAP);
    for (int i = tid; i < cnt; i += 256) {
        const int q = g_bins[bin * CAP + i];
        s_qid[i] = q;
        s_toi[i] = __ldg(reinterpret_cast<const int2*>(tois) + q);
    }

    // ---- Phase A: 8 warps x 8 d-rows; lane owns float4 of l (128 l total).
    // width-16 shuffle scan restarts exactly at the 64-l chunk boundary.
    #pragma unroll
    for (int r = 0; r < 8; r++) {
        const int dd = (w << 3) + r;                   // local d row 0..63
        const int dg = (h << 6) + dd;                  // global d
        const float4 v = *reinterpret_cast<const float4*>(
            feat + ((size_t)b * DD + dg) * LL + l0 + 4 * lane);
        const float i0 = v.x;
        const float i1 = i0 + v.y;
        const float i2 = i1 + v.z;
        const float i3 = i2 + v.w;
        float s = i3;
        #pragma unroll
        for (int o = 1; o < 16; o <<= 1) {
            const float t = __shfl_up_sync(0xffffffffu, s, o, 16);
            if ((lane & 15) >= o) s += t;
        }
        const float pre = s - i3;                      // exclusive prefix in chunk
        ic[dd][4 * lane    ] = pre + i0;
        ic[dd][4 * lane + 1] = pre + i1;
        ic[dd][4 * lane + 2] = pre + i2;
        ic[dd][4 * lane + 3] = pre + i3;
    }
    __syncthreads();

    // ---- Phase B: serve queries; 4 groups of 64 threads, one query each.
    const int grp = tid >> 6;          // 0..3
    const int t64 = tid & 63;          // local d

    for (int i = grp; i < cnt; i += 4) {
        const int q  = s_qid[i];
        const int2 t = s_toi[i];
        const int sL = t.x - l0;           // [0,64)
        const int eL = t.y - 1 - l0;       // [0,127]

        const float A  = ic[t64][sL];
        const float Bv = sL        ? ic[t64][sL - 1] : 0.0f;
        const float C  = ic[t64][eL];
        const float Dv = (eL & 63) ? ic[t64][eL - 1] : 0.0f;
        const float E  = (eL >= 64) ? ic[t64][63]    : 0.0f;

        const float head = A - Bv;
        const float tail = C - Dv;
        const float avg  = (C + E - Bv) / (float)(t.y - t.x);

        float* o = out + (size_t)q * (3 * DD) + (h << 6) + t64;
        o[0]      = head;
        o[DD]     = avg;
        o[2 * DD] = tail;
    }

    // counts output: cumsum of per-batch query counts = [N, 2N, ..., B*N]
    if (write_counts && c0 == 0 && h == 0 && b == 0 && tid < BB) {
        out[(size_t)BB * NQ * 3 * DD + tid] = (float)((tid + 1) * NQ);
    }
}

extern "C" void kernel_launch(void* const* d_in, const int* in_sizes, int n_in,
                              void* d_out, int out_size) {
    const float* feat = (const float*)d_in[0];
    const int*   tois = (const int*)d_in[1];
    float*       out  = (float*)d_out;

    const long long total = (long long)BB * NQ * 3 * DD;  // 50,331,648
    const int write_counts = ((long long)out_size >= total + BB) ? 1 : 0;

    k_prep<<<BB, 1024>>>(tois);

    dim3 g(CHUNKS, 4, BB);            // 63 x 4 x 16 = 4032 blocks
    k_main<<<g, 256>>>(feat, tois, out, write_counts);
}

// round 8
// speedup vs baseline: 1.1221x; 1.0005x over previous
#include <cuda_runtime.h>
#include <cstdint>

// Problem constants: features (B, D, L) f32, tois (B, N, 2) i32, MAX_SPAN=64
#define BB 16
#define DD 256
#define LL 4096
#define NQ 4096
#define CHUNKS 63            // c0 = start>>6 in [0,62] since start <= L-MAX_SPAN-1
#define CAP 192              // bin capacity; mean occupancy ~65, >10 sigma margin

__device__ int g_cnt[BB * CHUNKS];
__device__ int g_bins[BB * CHUNKS * CAP];

// Column permutation for the smem scan buffer: conflict-free on BOTH the
// phase-A row writes (banks (d+lane)%32) and phase-B column reads
// (banks (d+perm(l))%32). Bijection on [0,128).
#define PERM(l) ((((l) & 3) << 5) | ((l) >> 2))

// ---------------------------------------------------------------------------
// Prepass: per-batch binning, single pass (scatter counters ARE the counts).
// ---------------------------------------------------------------------------
__global__ void __launch_bounds__(1024) k_prep(const int* __restrict__ tois) {
    __shared__ int cur[CHUNKS];

    const int b   = blockIdx.x;
    const int tid = threadIdx.x;

    if (tid < CHUNKS) cur[tid] = 0;
    __syncthreads();

    #pragma unroll
    for (int k = 0; k < 4; k++) {
        const int n = tid + (k << 10);
        const int q = b * NQ + n;
        const int c = tois[2 * q] >> 6;
        const int p = atomicAdd(&cur[c], 1);
        if (p < CAP) g_bins[(b * CHUNKS + c) * CAP + p] = q;
    }
    __syncthreads();

    if (tid < CHUNKS) {
        const int v = cur[tid];
        g_cnt[b * CHUNKS + tid] = v < CAP ? v : CAP;
    }
}

// ---------------------------------------------------------------------------
// Main fused kernel. Block = (c0, d-slice h, b).
// Stage bin metadata into smem, chunk-local (64) inclusive scan of
// feat[l0..l0+128) x 64 d into permuted smem, serve queries from smem only.
// ---------------------------------------------------------------------------
__global__ void __launch_bounds__(256) k_main(const float* __restrict__ feat,
                                              const int* __restrict__ tois,
                                              float* __restrict__ out,
                                              int write_counts) {
    __shared__ float ic[64][129];     // [d][perm(l)]
    __shared__ int   s_qid[CAP];
    __shared__ int2  s_toi[CAP];

    const int c0 = blockIdx.x;        // 0..62
    const int h  = blockIdx.y;        // d slice 0..3
    const int b  = blockIdx.z;
    const int tid  = threadIdx.x;
    const int w    = tid >> 5;
    const int lane = tid & 31;
    const int l0   = c0 << 6;

    // ---- Stage bin metadata (g_cnt read is a broadcast).
    const int bin = b * CHUNKS + c0;
    const int cnt = min(g_cnt[bin], CAP);
    for (int i = tid; i < cnt; i += 256) {
        const int q = g_bins[bin * CAP + i];
        s_qid[i] = q;
        s_toi[i] = __ldg(reinterpret_cast<const int2*>(tois) + q);
    }

    // ---- Phase A: 8 warps x 8 d-rows; lane owns a float4 of l (128 l total).
    // width-16 shuffle scan restarts exactly at the 64-l chunk boundary.
    // Stores use the bit-rotate column perm: j-th store hits column j*32+lane
    // -> banks (dd+lane)%32, conflict-free.
    #pragma unroll
    for (int r = 0; r < 8; r++) {
        const int dd = (w << 3) + r;                   // local d row 0..63
        const int dg = (h << 6) + dd;                  // global d
        const float4 v = *reinterpret_cast<const float4*>(
            feat + ((size_t)b * DD + dg) * LL + l0 + 4 * lane);
        const float i0 = v.x;
        const float i1 = i0 + v.y;
        const float i2 = i1 + v.z;
        const float i3 = i2 + v.w;
        float s = i3;
        #pragma unroll
        for (int o = 1; o < 16; o <<= 1) {
            const float t = __shfl_up_sync(0xffffffffu, s, o, 16);
            if ((lane & 15) >= o) s += t;
        }
        const float pre = s - i3;                      // exclusive prefix in chunk
        ic[dd][       lane] = pre + i0;   // perm(4*lane+0)
        ic[dd][ 32 +  lane] = pre + i1;   // perm(4*lane+1)
        ic[dd][ 64 +  lane] = pre + i2;   // perm(4*lane+2)
        ic[dd][ 96 +  lane] = pre + i3;   // perm(4*lane+3)
    }
    __syncthreads();

    // ---- Phase B: serve queries; 4 groups of 64 threads, one query each.
    const int grp = tid >> 6;          // 0..3
    const int t64 = tid & 63;          // local d

    for (int i = grp; i < cnt; i += 4) {
        const int q  = s_qid[i];
        const int2 t = s_toi[i];
        const int sL = t.x - l0;           // [0,64)
        const int eL = t.y - 1 - l0;       // [0,127]

        const float A  = ic[t64][PERM(sL)];
        const float Bv = sL        ? ic[t64][PERM(sL - 1)] : 0.0f;
        const float C  = ic[t64][PERM(eL)];
        const float Dv = (eL & 63) ? ic[t64][PERM(eL - 1)] : 0.0f;
        const float E  = (eL >= 64) ? ic[t64][PERM(63)]    : 0.0f;

        const float head = A - Bv;
        const float tail = C - Dv;
        const float avg  = (C + E - Bv) / (float)(t.y - t.x);

        float* o = out + (size_t)q * (3 * DD) + (h << 6) + t64;
        o[0]      = head;
        o[DD]     = avg;
        o[2 * DD] = tail;
    }

    // counts output: cumsum of per-batch query counts = [N, 2N, ..., B*N]
    if (write_counts && c0 == 0 && h == 0 && b == 0 && tid < BB) {
        out[(size_t)BB * NQ * 3 * DD + tid] = (float)((tid + 1) * NQ);
    }
}

extern "C" void kernel_launch(void* const* d_in, const int* in_sizes, int n_in,
                              void* d_out, int out_size) {
    const float* feat = (const float*)d_in[0];
    const int*   tois = (const int*)d_in[1];
    float*       out  = (float*)d_out;

    const long long total = (long long)BB * NQ * 3 * DD;  // 50,331,648
    const int write_counts = ((long long)out_size >= total + BB) ? 1 : 0;

    k_prep<<<BB, 1024>>>(tois);

    dim3 g(CHUNKS, 4, BB);            // 63 x 4 x 16 = 4032 blocks
    k_main<<<g, 256>>>(feat, tois, out, write_counts);
}

// round 9
// speedup vs baseline: 1.2861x; 1.1462x over previous
#include <cuda_runtime.h>
#include <cstdint>

// Problem constants: features (B, D, L) f32, tois (B, N, 2) i32, MAX_SPAN=64
#define BB 16
#define DD 256
#define LL 4096
#define NQ 4096
#define CHUNKS 63            // c0 = start>>6 in [0,62] since start <= L-MAX_SPAN-1
#define SUBS 8               // n-subranges per batch (512 queries each)
#define SUBCAP 32            // per-sub-bin capacity; mean 8.1, ~8 sigma margin

// Sub-binned scratch: every cell written by exactly one block per launch via
// plain stores -> no zeroing kernel needed, fully deterministic outputs.
__device__ int g_cnt8[BB * CHUNKS * SUBS];
__device__ int g_bins[BB * CHUNKS * SUBS * SUBCAP];

// ---------------------------------------------------------------------------
// Prepass: (b, n-subrange) blocks bin their 512 queries by start-chunk.
// 128 blocks x 512 threads -> ~1 wave on 148 SMs.
// ---------------------------------------------------------------------------
__global__ void __launch_bounds__(512) k_prep(const int* __restrict__ tois) {
    __shared__ int cur[CHUNKS];

    const int b   = blockIdx.x;
    const int sub = blockIdx.y;
    const int tid = threadIdx.x;

    if (tid < CHUNKS) cur[tid] = 0;
    __syncthreads();

    const int q = b * NQ + (sub << 9) + tid;
    const int c = tois[2 * q] >> 6;
    const int p = atomicAdd(&cur[c], 1);
    if (p < SUBCAP)
        g_bins[(((b * CHUNKS + c) << 3) + sub) * SUBCAP + p] = q;
    __syncthreads();

    if (tid < CHUNKS) {
        const int v = cur[tid];
        g_cnt8[((b * CHUNKS + tid) << 3) + sub] = v < SUBCAP ? v : SUBCAP;
    }
}

// ---------------------------------------------------------------------------
// Main fused kernel. Block = (c0, 32-d slice h, b). 256 thr, 8 blocks/SM.
// Warp s stages sub-bin s; 8 warps x 4 d-rows scan feat[l0..l0+128);
// phase B: warp = one query at a time, lane owns d. Plain [d][129] layout:
// phase-B reads conflict-free, phase-A 4-way STS accepted (L1 has headroom).
// ---------------------------------------------------------------------------
__global__ void __launch_bounds__(256, 8) k_main(const float* __restrict__ feat,
                                                 const int* __restrict__ tois,
                                                 float* __restrict__ out,
                                                 int write_counts) {
    __shared__ float ic[32][129];     // [d][l]
    __shared__ int   s_qid[SUBS * SUBCAP];
    __shared__ int2  s_toi[SUBS * SUBCAP];
    __shared__ int   s_cnt[SUBS];
    __shared__ int   s_total;

    const int c0 = blockIdx.x;        // 0..62
    const int h  = blockIdx.y;        // d slice 0..7 (32 d each)
    const int b  = blockIdx.z;
    const int tid  = threadIdx.x;
    const int w    = tid >> 5;
    const int lane = tid & 31;
    const int l0   = c0 << 6;

    const int bin8 = (b * CHUNKS + c0) << 3;
    if (tid < SUBS) s_cnt[tid] = g_cnt8[bin8 + tid];
    __syncthreads();

    // ---- Stage: warp s compacts sub-bin s into s_qid/s_toi (lane-parallel).
    {
        int off = 0;
        #pragma unroll
        for (int k = 0; k < SUBS; k++) off += (k < w) ? s_cnt[k] : 0;
        const int cs = s_cnt[w];
        if (w == SUBS - 1 && lane == 0) s_total = off + cs;
        if (lane < cs) {
            const int q = g_bins[(bin8 + w) * SUBCAP + lane];
            s_qid[off + lane] = q;
            s_toi[off + lane] = __ldg(reinterpret_cast<const int2*>(tois) + q);
        }
    }

    // ---- Phase A: 8 warps x 4 d-rows; lane owns a float4 of l (128 l).
    // width-16 shuffle scan restarts exactly at the 64-l chunk boundary.
    #pragma unroll
    for (int r = 0; r < 4; r++) {
        const int dd = (w << 2) + r;                   // local d row 0..31
        const int dg = (h << 5) + dd;                  // global d
        const float4 v = *reinterpret_cast<const float4*>(
            feat + ((size_t)b * DD + dg) * LL + l0 + 4 * lane);
        const float i0 = v.x;
        const float i1 = i0 + v.y;
        const float i2 = i1 + v.z;
        const float i3 = i2 + v.w;
        float s = i3;
        #pragma unroll
        for (int o = 1; o < 16; o <<= 1) {
            const float t = __shfl_up_sync(0xffffffffu, s, o, 16);
            if ((lane & 15) >= o) s += t;
        }
        const float pre = s - i3;                      // exclusive prefix in chunk
        ic[dd][4 * lane    ] = pre + i0;
        ic[dd][4 * lane + 1] = pre + i1;
        ic[dd][4 * lane + 2] = pre + i2;
        ic[dd][4 * lane + 3] = pre + i3;
    }
    __syncthreads();

    // ---- Phase B: one query per warp per iteration; lane owns local d.
    const int total = s_total;

    #pragma unroll 2
    for (int i = w; i < total; i += 8) {
        const int q  = s_qid[i];
        const int2 t = s_toi[i];
        const int sL = t.x - l0;           // [0,64)
        const int eL = t.y - 1 - l0;       // [0,127]

        const float A  = ic[lane][sL];
        const float Bv = sL        ? ic[lane][sL - 1] : 0.0f;
        const float C  = ic[lane][eL];
        const float Dv = (eL & 63) ? ic[lane][eL - 1] : 0.0f;
        const float E  = (eL >= 64) ? ic[lane][63]    : 0.0f;

        const float head = A - Bv;
        const float tail = C - Dv;
        const float avg  = (C + E - Bv) / (float)(t.y - t.x);

        float* o = out + (size_t)q * (3 * DD) + (h << 5) + lane;
        o[0]      = head;
        o[DD]     = avg;
        o[2 * DD] = tail;
    }

    // counts output: cumsum of per-batch query counts = [N, 2N, ..., B*N]
    if (write_counts && c0 == 0 && h == 0 && b == 0 && tid < BB) {
        out[(size_t)BB * NQ * 3 * DD + tid] = (float)((tid + 1) * NQ);
    }
}

extern "C" void kernel_launch(void* const* d_in, const int* in_sizes, int n_in,
                              void* d_out, int out_size) {
    const float* feat = (const float*)d_in[0];
    const int*   tois = (const int*)d_in[1];
    float*       out  = (float*)d_out;

    const long long total = (long long)BB * NQ * 3 * DD;  // 50,331,648
    const int write_counts = ((long long)out_size >= total + BB) ? 1 : 0;

    dim3 gp(BB, SUBS);                 // 128 blocks
    k_prep<<<gp, 512>>>(tois);

    dim3 g(CHUNKS, 8, BB);             // 63 x 8 x 16 = 8064 blocks
    k_main<<<g, 256>>>(feat, tois, out, write_counts);
}